// round 2
// baseline (speedup 1.0000x reference)
#include <cuda_runtime.h>
#include <cstddef>

#define NMAX 100000
#define EMAX 600000
#define NG   256
#define DH   128
#define H4   512
#define BN_EPS 1e-5f
#define GN_EPS 1e-5f

// ---------------- static device scratch (no runtime alloc allowed) ----------------
static __device__ float g_A [(size_t)NMAX * DH];   // h + agg  (GEMM1 input)
static __device__ float g_z1[(size_t)NMAX * H4];   // GEMM1 output
static __device__ float g_z2[(size_t)NMAX * DH];   // GEMM2 output
static __device__ float g_h [(size_t)NMAX * DH];   // layer output / next input
static __device__ int   g_rowptr[NMAX + 1];
static __device__ int   g_cursor[NMAX];
static __device__ int   g_colidx[EMAX];
static __device__ int   g_bsum[128];
static __device__ int   g_boff[128];
static __device__ int   g_gstart[NG + 1];
static __device__ float g_invcnt[NG];
static __device__ float g_bnstat[2 * H4];          // [0..511]=sum, [512..1023]=sumsq
static __device__ float g_scale[H4];
static __device__ float g_shift[H4];
static __device__ float g_gm[NG * DH];
static __device__ float g_GS[NG * DH];
static __device__ float g_GB[NG * DH];
static __device__ int   g_i64;

// ---------------- helpers ----------------
__device__ __forceinline__ float selu_f(float x) {
    const float lam = 1.0507009873554805f;
    const float la  = 1.7580993408473766f;   // lam * alpha
    return x > 0.f ? lam * x : la * (__expf(x) - 1.f);
}

// packed fp32x2 FMA (Blackwell dual-pumped fp32 path, PTX ISA 8.6 / sm_100+)
__device__ __forceinline__ unsigned long long pk2(float lo, float hi) {
    unsigned long long r;
    asm("mov.b64 %0, {%1, %2};" : "=l"(r) : "f"(lo), "f"(hi));
    return r;
}
__device__ __forceinline__ unsigned long long fma2(unsigned long long a,
                                                   unsigned long long b,
                                                   unsigned long long c) {
    unsigned long long d;
    asm("fma.rn.f32x2 %0, %1, %2, %3;" : "=l"(d) : "l"(a), "l"(b), "l"(c));
    return d;
}
__device__ __forceinline__ float2 upk2(unsigned long long v) {
    float2 r;
    asm("mov.b64 {%0, %1}, %2;" : "=f"(r.x), "=f"(r.y) : "l"(v));
    return r;
}

// read an index that might be int64 or int32 underneath (jax x64 ambiguity)
__device__ __forceinline__ int readIdx(const void* p, long long i) {
    return g_i64 ? (int)((const long long*)p)[i] : ((const int*)p)[i];
}

// ---------------- tiny utility kernels ----------------
__global__ void zero_f_k(float* p, int n) {
    int i = blockIdx.x * blockDim.x + threadIdx.x;
    if (i < n) p[i] = 0.f;
}
__global__ void zero_i_k(int* p, int n) {
    int i = blockIdx.x * blockDim.x + threadIdx.x;
    if (i < n) p[i] = 0;
}
__global__ void detect_kernel(const void* ei) {
    if (threadIdx.x == 0) {
        const long long* p = (const long long*)ei;
        int ok = 1;
        for (int i = 0; i < 64; i++) {
            long long v = p[i];
            if (v < 0 || v >= (1LL << 31)) ok = 0;
        }
        g_i64 = ok;
    }
}

// ---------------- CSR build ----------------
__global__ void hist_kernel(const void* ei, int E) {
    int e = blockIdx.x * blockDim.x + threadIdx.x;
    if (e < E) atomicAdd(&g_cursor[readIdx(ei, (long long)E + e)], 1);
}
__global__ void scan1_kernel(int n) {
    __shared__ int s[1024];
    int tid = threadIdx.x;
    int i = blockIdx.x * 1024 + tid;
    int v = (i < n) ? g_cursor[i] : 0;
    s[tid] = v;
    __syncthreads();
    for (int off = 1; off < 1024; off <<= 1) {
        int t = 0;
        if (tid >= off) t = s[tid - off];
        __syncthreads();
        s[tid] += t;
        __syncthreads();
    }
    if (i < n) g_rowptr[i + 1] = s[tid];
    if (tid == 1023) g_bsum[blockIdx.x] = s[1023];
}
__global__ void scan2_kernel(int nb) {
    if (threadIdx.x == 0) {
        int run = 0;
        for (int b = 0; b < nb; b++) { g_boff[b] = run; run += g_bsum[b]; }
    }
}
__global__ void scan3_kernel(int n) {
    int i = blockIdx.x * blockDim.x + threadIdx.x;
    if (i < n) g_rowptr[i + 1] += g_boff[i >> 10];
    if (i == 0) g_rowptr[0] = 0;
}
__global__ void scatter_kernel(const void* ei, int E) {
    int e = blockIdx.x * blockDim.x + threadIdx.x;
    if (e >= E) return;
    int d = readIdx(ei, (long long)E + e);
    int slot = g_rowptr[d] + atomicAdd(&g_cursor[d], 1);
    g_colidx[slot] = readIdx(ei, e);
}

// ---------------- graph ranges (batch is sorted) ----------------
__global__ void gstart_kernel(const void* batch, int n) {
    int g = blockIdx.x * blockDim.x + threadIdx.x;
    if (g > NG) return;
    int lo = 0, hi = n;
    while (lo < hi) {
        int mid = (lo + hi) >> 1;
        if (readIdx(batch, mid) < g) lo = mid + 1; else hi = mid;
    }
    g_gstart[g] = lo;
}
__global__ void invcnt_kernel() {
    int g = threadIdx.x;
    if (g < NG) {
        int c = g_gstart[g + 1] - g_gstart[g];
        g_invcnt[g] = 1.f / fmaxf((float)c, 1.f);
    }
}

// ---------------- GIN aggregation: g_A = h + sum_{j in in(i)} h[j] ----------------
__global__ void agg_kernel(const float* __restrict__ h, int N) {
    int warp = (blockIdx.x * blockDim.x + threadIdx.x) >> 5;
    int lane = threadIdx.x & 31;
    if (warp >= N) return;
    float4 acc = __ldg((const float4*)(h + (size_t)warp * DH) + lane);
    int s = g_rowptr[warp], e = g_rowptr[warp + 1];
    for (int p = s; p < e; ++p) {
        int nb = g_colidx[p];
        float4 v = __ldg((const float4*)(h + (size_t)nb * DH) + lane);
        acc.x += v.x; acc.y += v.y; acc.z += v.z; acc.w += v.w;
    }
    ((float4*)(g_A + (size_t)warp * DH))[lane] = acc;
}

// ---------------- tiled fp32x2 GEMM: C = act(A) @ W^T (+bias / +BN stats) ----------
// PRO: 0 = none, 1 = apply BN scale/shift + SELU on A load
// EPI: 1 = write + accumulate per-column sum/sumsq, 2 = +bias write
template <int PRO, int EPI>
__global__ void __launch_bounds__(256, 2)
gemm_kernel(const float* __restrict__ A, const float* __restrict__ W,
            float* __restrict__ C, int M, int Ncols, int K,
            const float* __restrict__ bias) {
    __shared__ float As[32][132];
    __shared__ float Bs[32][132];
    int tid = threadIdx.x;
    int tx = tid & 15, ty = tid >> 4;
    int rowBase = blockIdx.x * 128;
    int colBase = blockIdx.y * 128;
    int m0 = ty * 8, n0 = tx * 8;

    unsigned long long Cr[8][4];
#pragma unroll
    for (int i = 0; i < 8; i++)
#pragma unroll
        for (int j = 0; j < 4; j++) Cr[i][j] = 0ULL;

    int nk = K >> 5;
    for (int kt = 0; kt < nk; kt++) {
#pragma unroll
        for (int it = 0; it < 4; it++) {
            int chunk = tid + it * 256;
            int row = chunk >> 3, kq = chunk & 7;
            int kg = (kt << 5) + (kq << 2);
            int r = rowBase + row;
            float4 v = make_float4(0.f, 0.f, 0.f, 0.f);
            if (r < M) v = *(const float4*)(A + (size_t)r * K + kg);
            if (PRO == 1) {
                v.x = selu_f(fmaf(v.x, g_scale[kg + 0], g_shift[kg + 0]));
                v.y = selu_f(fmaf(v.y, g_scale[kg + 1], g_shift[kg + 1]));
                v.z = selu_f(fmaf(v.z, g_scale[kg + 2], g_shift[kg + 2]));
                v.w = selu_f(fmaf(v.w, g_scale[kg + 3], g_shift[kg + 3]));
            }
            As[kq * 4 + 0][row] = v.x;
            As[kq * 4 + 1][row] = v.y;
            As[kq * 4 + 2][row] = v.z;
            As[kq * 4 + 3][row] = v.w;
            float4 w = *(const float4*)(W + (size_t)(colBase + row) * K + kg);
            Bs[kq * 4 + 0][row] = w.x;
            Bs[kq * 4 + 1][row] = w.y;
            Bs[kq * 4 + 2][row] = w.z;
            Bs[kq * 4 + 3][row] = w.w;
        }
        __syncthreads();
#pragma unroll 8
        for (int k = 0; k < 32; k++) {
            float4 a0 = *(const float4*)&As[k][m0];
            float4 a1 = *(const float4*)&As[k][m0 + 4];
            ulonglong2 bA = *(const ulonglong2*)&Bs[k][n0];
            ulonglong2 bB = *(const ulonglong2*)&Bs[k][n0 + 4];
            unsigned long long bp[4] = {bA.x, bA.y, bB.x, bB.y};
            unsigned long long ap[8] = {
                pk2(a0.x, a0.x), pk2(a0.y, a0.y), pk2(a0.z, a0.z), pk2(a0.w, a0.w),
                pk2(a1.x, a1.x), pk2(a1.y, a1.y), pk2(a1.z, a1.z), pk2(a1.w, a1.w)};
#pragma unroll
            for (int i = 0; i < 8; i++)
#pragma unroll
                for (int j = 0; j < 4; j++)
                    Cr[i][j] = fma2(ap[i], bp[j], Cr[i][j]);
        }
        __syncthreads();
    }

    if (EPI == 2) {
#pragma unroll
        for (int j = 0; j < 4; j++) {
            int c = colBase + n0 + 2 * j;
            float bx = bias[c], by = bias[c + 1];
#pragma unroll
            for (int i = 0; i < 8; i++) {
                float2 v = upk2(Cr[i][j]);
                v.x += bx; v.y += by;
                int r = rowBase + m0 + i;
                if (r < M) *(float2*)(C + (size_t)r * Ncols + c) = v;
            }
        }
    } else {
        float s[8], q[8];
#pragma unroll
        for (int jj = 0; jj < 8; jj++) { s[jj] = 0.f; q[jj] = 0.f; }
#pragma unroll
        for (int i = 0; i < 8; i++) {
            int r = rowBase + m0 + i;
            bool valid = r < M;
#pragma unroll
            for (int j = 0; j < 4; j++) {
                float2 v = upk2(Cr[i][j]);
                if (valid) *(float2*)(C + (size_t)r * Ncols + colBase + n0 + 2 * j) = v;
                s[2 * j]     += v.x; q[2 * j]     += v.x * v.x;
                s[2 * j + 1] += v.y; q[2 * j + 1] += v.y * v.y;
            }
        }
        // padded rows contribute exact zeros (A tile was zero-filled) -> safe
        float* red = &As[0][0];
        __syncthreads();
#pragma unroll
        for (int jj = 0; jj < 8; jj++) red[ty * 128 + n0 + jj] = s[jj];
        __syncthreads();
        if (tid < 128) {
            float t = 0.f;
#pragma unroll
            for (int u = 0; u < 16; u++) t += red[u * 128 + tid];
            atomicAdd(&g_bnstat[colBase + tid], t);
        }
        __syncthreads();
#pragma unroll
        for (int jj = 0; jj < 8; jj++) red[ty * 128 + n0 + jj] = q[jj];
        __syncthreads();
        if (tid < 128) {
            float t = 0.f;
#pragma unroll
            for (int u = 0; u < 16; u++) t += red[u * 128 + tid];
            atomicAdd(&g_bnstat[H4 + colBase + tid], t);
        }
    }
}

// ---------------- BN finalize: scale/shift per feature ----------------
__global__ void bnfin_kernel(const float* __restrict__ bn_g,
                             const float* __restrict__ bn_b, float fN) {
    int o = blockIdx.x * blockDim.x + threadIdx.x;
    if (o >= H4) return;
    float mu = g_bnstat[o] / fN;
    float var = fmaxf(g_bnstat[H4 + o] / fN - mu * mu, 0.f);
    float rstd = rsqrtf(var + BN_EPS);
    float sc = bn_g[o] * rstd;
    g_scale[o] = sc;
    g_shift[o] = bn_b[o] - mu * sc;
}

// ---------------- GraphNorm (one block per graph; batch sorted) ----------------
__global__ void gmean_kernel() {
    int g = blockIdx.x, f = threadIdx.x;
    int s = g_gstart[g], e = g_gstart[g + 1];
    float acc = 0.f;
#pragma unroll 4
    for (int r = s; r < e; ++r) acc += g_z2[(size_t)r * DH + f];
    g_gm[g * DH + f] = acc * g_invcnt[g];
}
__global__ void gvar_kernel(const float* __restrict__ gn_g,
                            const float* __restrict__ gn_b,
                            const float* __restrict__ gn_a) {
    int g = blockIdx.x, f = threadIdx.x;
    int s = g_gstart[g], e = g_gstart[g + 1];
    float am = gn_a[f] * g_gm[g * DH + f];
    float acc = 0.f;
#pragma unroll 4
    for (int r = s; r < e; ++r) {
        float d = g_z2[(size_t)r * DH + f] - am;
        acc += d * d;
    }
    float rstd = rsqrtf(acc * g_invcnt[g] + GN_EPS);
    float GS = gn_g[f] * rstd;
    g_GS[g * DH + f] = GS;
    g_GB[g * DH + f] = gn_b[f] - am * GS;
}
__global__ void final_kernel(float* __restrict__ out, int l) {
    int g = blockIdx.x, f = threadIdx.x;
    int s = g_gstart[g], e = g_gstart[g + 1];
    float GS = g_GS[g * DH + f], GB = g_GB[g * DH + f];
    float acc = 0.f;
#pragma unroll 4
    for (int r = s; r < e; ++r) {
        float val = selu_f(fmaf(g_z2[(size_t)r * DH + f], GS, GB));
        g_h[(size_t)r * DH + f] = val;
        acc += val;
    }
    out[(size_t)g * H4 + l * DH + f] = acc * g_invcnt[g];
}

// ---------------- launch ----------------
extern "C" void kernel_launch(void* const* d_in, const int* in_sizes, int n_in,
                              void* d_out, int out_size) {
    const float* x    = (const float*)d_in[0];
    const float* W1   = (const float*)d_in[1];
    const float* bn_g = (const float*)d_in[2];
    const float* bn_b = (const float*)d_in[3];
    const float* W2   = (const float*)d_in[4];
    const float* b2   = (const float*)d_in[5];
    const float* gn_g = (const float*)d_in[6];
    const float* gn_b = (const float*)d_in[7];
    const float* gn_a = (const float*)d_in[8];
    const void*  ei   = d_in[9];
    const void*  batch= d_in[10];
    int N = in_sizes[0] / DH;
    int E = in_sizes[9] / 2;
    float* out = (float*)d_out;

    float *pA, *pz1, *pz2, *ph, *pbn;
    int* pcur;
    cudaGetSymbolAddress((void**)&pA,  g_A);
    cudaGetSymbolAddress((void**)&pz1, g_z1);
    cudaGetSymbolAddress((void**)&pz2, g_z2);
    cudaGetSymbolAddress((void**)&ph,  g_h);
    cudaGetSymbolAddress((void**)&pbn, g_bnstat);
    cudaGetSymbolAddress((void**)&pcur, g_cursor);

    // int width detection + CSR build
    detect_kernel<<<1, 32>>>(ei);
    zero_i_k<<<(N + 255) / 256, 256>>>(pcur, N);
    hist_kernel<<<(E + 255) / 256, 256>>>(ei, E);
    int nb = (N + 1023) / 1024;
    scan1_kernel<<<nb, 1024>>>(N);
    scan2_kernel<<<1, 32>>>(nb);
    scan3_kernel<<<(N + 255) / 256, 256>>>(N);
    zero_i_k<<<(N + 255) / 256, 256>>>(pcur, N);
    scatter_kernel<<<(E + 255) / 256, 256>>>(ei, E);
    gstart_kernel<<<2, 256>>>(batch, N);
    invcnt_kernel<<<1, 256>>>();

    int gm = (N + 127) / 128;
    for (int l = 0; l < 4; l++) {
        const float* hin = l ? (const float*)ph : x;
        agg_kernel<<<(N + 7) / 8, 256>>>(hin, N);
        zero_f_k<<<4, 256>>>(pbn, 2 * H4);
        gemm_kernel<0, 1><<<dim3(gm, 4), 256>>>(
            pA, W1 + (size_t)l * H4 * DH, pz1, N, H4, DH, nullptr);
        bnfin_kernel<<<1, 512>>>(bn_g + l * H4, bn_b + l * H4, (float)N);
        gemm_kernel<1, 2><<<dim3(gm, 1), 256>>>(
            pz1, W2 + (size_t)l * DH * H4, pz2, N, DH, H4, b2 + l * DH);
        gmean_kernel<<<NG, 128>>>();
        gvar_kernel<<<NG, 128>>>(gn_g + l * DH, gn_b + l * DH, gn_a + l * DH);
        final_kernel<<<NG, 128>>>(out, l);
    }
}

// round 4
// speedup vs baseline: 1.2125x; 1.2125x over previous
#include <cuda_runtime.h>
#include <cuda_bf16.h>
#include <mma.h>
#include <cstdint>
#include <cstddef>

#define NMAX 100000
#define EMAX 600000
#define NG   256
#define DH   128
#define H4   512
#define BN_EPS 1e-5f
#define GN_EPS 1e-5f

using namespace nvcuda;

// ---------------- static device scratch ----------------
static __device__ float g_A [(size_t)NMAX * DH];
static __device__ float g_z1[(size_t)NMAX * H4];
static __device__ float g_z2[(size_t)NMAX * DH];
static __device__ float g_h [(size_t)NMAX * DH];
static __device__ int   g_rowptr[NMAX + 1];
static __device__ int   g_cursor[NMAX];
static __device__ int   g_colidx[EMAX];
static __device__ int   g_bsum[128];
static __device__ int   g_boff[128];
static __device__ int   g_gstart[NG + 1];
static __device__ float g_invcnt[NG];
static __device__ float g_bnstat[2 * H4];
static __device__ float g_scale[H4];
static __device__ float g_shift[H4];
static __device__ float g_gm[NG * DH];
static __device__ float g_GS[NG * DH];
static __device__ float g_GB[NG * DH];
static __device__ int   g_i64;

// ---------------- helpers ----------------
__device__ __forceinline__ float selu_f(float x) {
    const float lam = 1.0507009873554805f;
    const float la  = 1.7580993408473766f;
    return x > 0.f ? lam * x : la * (__expf(x) - 1.f);
}
__device__ __forceinline__ int readIdx(const void* p, long long i) {
    return g_i64 ? (int)((const long long*)p)[i] : ((const int*)p)[i];
}
// split fp32 pair -> packed bf16x2 hi + residual lo (elem0 in low half)
__device__ __forceinline__ void split2(float a, float b, uint32_t& hi, uint32_t& lo) {
    uint32_t h;
    asm("cvt.rn.bf16x2.f32 %0, %1, %2;" : "=r"(h) : "f"(b), "f"(a));
    float fa = __uint_as_float(h << 16);
    float fb = __uint_as_float(h & 0xffff0000u);
    float ra = a - fa, rb = b - fb;
    uint32_t l;
    asm("cvt.rn.bf16x2.f32 %0, %1, %2;" : "=r"(l) : "f"(rb), "f"(ra));
    hi = h; lo = l;
}

// smem layout for mgemm (bytes)
#define LDA 72           // bf16 elements per padded tile row
#define TILE_B (128 * LDA * 2)      // 18432
#define OFF_AH 0
#define OFF_AL (TILE_B)
#define OFF_BH (2 * TILE_B)
#define OFF_BL (3 * TILE_B)
#define LDC 132
#define SMEM_GEMM (4 * TILE_B)      // 73728 > 128*132*4 = 67584 (C reuse)

// load 128x64 fp32 slab -> split hi/lo bf16 padded tiles
template <int PRO>
__device__ __forceinline__ void load_tile(const float* __restrict__ src, int ld,
                                          int rowBase, int rowLim, int kbase,
                                          __nv_bfloat16* dhi, __nv_bfloat16* dlo,
                                          int tid) {
#pragma unroll
    for (int i = 0; i < 4; i++) {
        int c = tid + i * 256;
        int row = c >> 3, k8 = c & 7;
        int gr = rowBase + row;
        float v[8];
        if (gr < rowLim) {
            const float4* p = (const float4*)(src + (size_t)gr * ld + kbase + k8 * 8);
            float4 u0 = p[0], u1 = p[1];
            v[0] = u0.x; v[1] = u0.y; v[2] = u0.z; v[3] = u0.w;
            v[4] = u1.x; v[5] = u1.y; v[6] = u1.z; v[7] = u1.w;
        } else {
#pragma unroll
            for (int j = 0; j < 8; j++) v[j] = 0.f;
        }
        if (PRO) {
            int col = kbase + k8 * 8;
#pragma unroll
            for (int j = 0; j < 8; j++)
                v[j] = selu_f(fmaf(v[j], g_scale[col + j], g_shift[col + j]));
        }
        uint32_t h[4], l[4];
#pragma unroll
        for (int j = 0; j < 4; j++) split2(v[2 * j], v[2 * j + 1], h[j], l[j]);
        *(uint4*)(dhi + row * LDA + k8 * 8) = make_uint4(h[0], h[1], h[2], h[3]);
        *(uint4*)(dlo + row * LDA + k8 * 8) = make_uint4(l[0], l[1], l[2], l[3]);
    }
}

// ---------------- WMMA split-bf16 GEMM: C[M,Ncols] = A[M,K] @ B[Ncols,K]^T ----------
// EPI 1: write C + BN sum/sumsq atomics.  EPI 2: write C + bias.
template <int EPI, int PRO>
__global__ void __launch_bounds__(256)
mgemm(const float* __restrict__ A, const float* __restrict__ B, float* __restrict__ C,
      int M, int K, int Ncols, const float* __restrict__ bias) {
    extern __shared__ char sm[];
    __nv_bfloat16* Ah = (__nv_bfloat16*)(sm + OFF_AH);
    __nv_bfloat16* Al = (__nv_bfloat16*)(sm + OFF_AL);
    __nv_bfloat16* Bh = (__nv_bfloat16*)(sm + OFF_BH);
    __nv_bfloat16* Bl = (__nv_bfloat16*)(sm + OFF_BL);
    float* Csm = (float*)sm;

    int tid = threadIdx.x;
    int w = tid >> 5;
    int m0 = (w >> 2) * 64;     // warp m offset within 128 tile
    int n0 = (w & 3) * 32;      // warp n offset
    int rowBase = blockIdx.y * 128;
    int colBase = blockIdx.x * 128;

    wmma::fragment<wmma::accumulator, 16, 16, 16, float> acc[4][2];
#pragma unroll
    for (int mi = 0; mi < 4; mi++)
#pragma unroll
        for (int ni = 0; ni < 2; ni++) wmma::fill_fragment(acc[mi][ni], 0.f);

    for (int kb = 0; kb < K; kb += 64) {
        __syncthreads();
        load_tile<PRO>(A, K, rowBase, M, kb, Ah, Al, tid);
        load_tile<0>(B, K, colBase, 1 << 30, kb, Bh, Bl, tid);
        __syncthreads();
#pragma unroll
        for (int ks = 0; ks < 4; ks++) {
            wmma::fragment<wmma::matrix_b, 16, 16, 16, __nv_bfloat16, wmma::col_major> bh[2], bl[2];
#pragma unroll
            for (int ni = 0; ni < 2; ni++) {
                wmma::load_matrix_sync(bh[ni], Bh + (n0 + 16 * ni) * LDA + ks * 16, LDA);
                wmma::load_matrix_sync(bl[ni], Bl + (n0 + 16 * ni) * LDA + ks * 16, LDA);
            }
#pragma unroll
            for (int mi = 0; mi < 4; mi++) {
                wmma::fragment<wmma::matrix_a, 16, 16, 16, __nv_bfloat16, wmma::row_major> ah, al;
                wmma::load_matrix_sync(ah, Ah + (m0 + 16 * mi) * LDA + ks * 16, LDA);
                wmma::load_matrix_sync(al, Al + (m0 + 16 * mi) * LDA + ks * 16, LDA);
#pragma unroll
                for (int ni = 0; ni < 2; ni++) {
                    wmma::mma_sync(acc[mi][ni], ah, bh[ni], acc[mi][ni]);
                    wmma::mma_sync(acc[mi][ni], ah, bl[ni], acc[mi][ni]);
                    wmma::mma_sync(acc[mi][ni], al, bh[ni], acc[mi][ni]);
                }
            }
        }
    }

    // -------- epilogue: stage in smem, write C (+bias), BN stats --------
    __syncthreads();
#pragma unroll
    for (int mi = 0; mi < 4; mi++)
#pragma unroll
        for (int ni = 0; ni < 2; ni++)
            wmma::store_matrix_sync(Csm + (m0 + 16 * mi) * LDC + n0 + 16 * ni,
                                    acc[mi][ni], LDC, wmma::mem_row_major);
    __syncthreads();

    {
        int row = tid >> 1;
        int cb = (tid & 1) * 64;
        int grow = rowBase + row;
        if (grow < M) {
            float* dst = C + (size_t)grow * Ncols + colBase + cb;
            const float* srcr = Csm + row * LDC + cb;
#pragma unroll
            for (int j = 0; j < 64; j += 4) {
                float4 v = *(const float4*)(srcr + j);
                if (EPI == 2) {
                    v.x += __ldg(&bias[colBase + cb + j + 0]);
                    v.y += __ldg(&bias[colBase + cb + j + 1]);
                    v.z += __ldg(&bias[colBase + cb + j + 2]);
                    v.w += __ldg(&bias[colBase + cb + j + 3]);
                }
                *(float4*)(dst + j) = v;
            }
        }
    }
    if (EPI == 1) {
        int c = tid & 127;
        int r0 = (tid >> 7) * 64;
        float s = 0.f, q = 0.f;
#pragma unroll 4
        for (int r = r0; r < r0 + 64; r++) {
            float v = Csm[r * LDC + c];
            s += v; q += v * v;
        }
        atomicAdd(&g_bnstat[colBase + c], s);
        atomicAdd(&g_bnstat[H4 + colBase + c], q);
    }
}

// ---------------- tiny utility kernels ----------------
__global__ void zero_f_k(float* p, int n) {
    int i = blockIdx.x * blockDim.x + threadIdx.x;
    if (i < n) p[i] = 0.f;
}
__global__ void zero_i_k(int* p, int n) {
    int i = blockIdx.x * blockDim.x + threadIdx.x;
    if (i < n) p[i] = 0;
}
__global__ void detect_kernel(const void* ei) {
    if (threadIdx.x == 0) {
        const long long* p = (const long long*)ei;
        int ok = 1;
        for (int i = 0; i < 64; i++) {
            long long v = p[i];
            if (v < 0 || v >= (1LL << 31)) ok = 0;
        }
        g_i64 = ok;
    }
}

// ---------------- CSR build ----------------
__global__ void hist_kernel(const void* ei, int E) {
    int e = blockIdx.x * blockDim.x + threadIdx.x;
    if (e < E) atomicAdd(&g_cursor[readIdx(ei, (long long)E + e)], 1);
}
__global__ void scan1_kernel(int n) {
    __shared__ int s[1024];
    int tid = threadIdx.x;
    int i = blockIdx.x * 1024 + tid;
    int v = (i < n) ? g_cursor[i] : 0;
    s[tid] = v;
    __syncthreads();
    for (int off = 1; off < 1024; off <<= 1) {
        int t = 0;
        if (tid >= off) t = s[tid - off];
        __syncthreads();
        s[tid] += t;
        __syncthreads();
    }
    if (i < n) g_rowptr[i + 1] = s[tid];
    if (tid == 1023) g_bsum[blockIdx.x] = s[1023];
}
__global__ void scan2_kernel(int nb) {
    if (threadIdx.x == 0) {
        int run = 0;
        for (int b = 0; b < nb; b++) { g_boff[b] = run; run += g_bsum[b]; }
    }
}
__global__ void scan3_kernel(int n) {
    int i = blockIdx.x * blockDim.x + threadIdx.x;
    if (i < n) g_rowptr[i + 1] += g_boff[i >> 10];
    if (i == 0) g_rowptr[0] = 0;
}
__global__ void scatter_kernel(const void* ei, int E) {
    int e = blockIdx.x * blockDim.x + threadIdx.x;
    if (e >= E) return;
    int d = readIdx(ei, (long long)E + e);
    int slot = g_rowptr[d] + atomicAdd(&g_cursor[d], 1);
    g_colidx[slot] = readIdx(ei, e);
}

// ---------------- graph ranges ----------------
__global__ void gstart_kernel(const void* batch, int n) {
    int g = blockIdx.x * blockDim.x + threadIdx.x;
    if (g > NG) return;
    int lo = 0, hi = n;
    while (lo < hi) {
        int mid = (lo + hi) >> 1;
        if (readIdx(batch, mid) < g) lo = mid + 1; else hi = mid;
    }
    g_gstart[g] = lo;
}
__global__ void invcnt_kernel() {
    int g = threadIdx.x;
    if (g < NG) {
        int c = g_gstart[g + 1] - g_gstart[g];
        g_invcnt[g] = 1.f / fmaxf((float)c, 1.f);
    }
}

// ---------------- GIN aggregation ----------------
__global__ void agg_kernel(const float* __restrict__ h, int N) {
    int warp = (blockIdx.x * blockDim.x + threadIdx.x) >> 5;
    int lane = threadIdx.x & 31;
    if (warp >= N) return;
    float4 acc = __ldg((const float4*)(h + (size_t)warp * DH) + lane);
    int s = g_rowptr[warp], e = g_rowptr[warp + 1];
    for (int p = s; p < e; ++p) {
        int nb = g_colidx[p];
        float4 v = __ldg((const float4*)(h + (size_t)nb * DH) + lane);
        acc.x += v.x; acc.y += v.y; acc.z += v.z; acc.w += v.w;
    }
    ((float4*)(g_A + (size_t)warp * DH))[lane] = acc;
}

// ---------------- BN finalize ----------------
__global__ void bnfin_kernel(const float* __restrict__ bn_g,
                             const float* __restrict__ bn_b, float fN) {
    int o = blockIdx.x * blockDim.x + threadIdx.x;
    if (o >= H4) return;
    float mu = g_bnstat[o] / fN;
    float var = fmaxf(g_bnstat[H4 + o] / fN - mu * mu, 0.f);
    float rstd = rsqrtf(var + BN_EPS);
    float sc = bn_g[o] * rstd;
    g_scale[o] = sc;
    g_shift[o] = bn_b[o] - mu * sc;
}

// ---------------- GraphNorm ----------------
__global__ void gmean_kernel() {
    int g = blockIdx.x, f = threadIdx.x;
    int s = g_gstart[g], e = g_gstart[g + 1];
    float acc = 0.f;
#pragma unroll 4
    for (int r = s; r < e; ++r) acc += g_z2[(size_t)r * DH + f];
    g_gm[g * DH + f] = acc * g_invcnt[g];
}
__global__ void gvar_kernel(const float* __restrict__ gn_g,
                            const float* __restrict__ gn_b,
                            const float* __restrict__ gn_a) {
    int g = blockIdx.x, f = threadIdx.x;
    int s = g_gstart[g], e = g_gstart[g + 1];
    float am = gn_a[f] * g_gm[g * DH + f];
    float acc = 0.f;
#pragma unroll 4
    for (int r = s; r < e; ++r) {
        float d = g_z2[(size_t)r * DH + f] - am;
        acc += d * d;
    }
    float rstd = rsqrtf(acc * g_invcnt[g] + GN_EPS);
    float GS = gn_g[f] * rstd;
    g_GS[g * DH + f] = GS;
    g_GB[g * DH + f] = gn_b[f] - am * GS;
}
__global__ void final_kernel(float* __restrict__ out, int l) {
    int g = blockIdx.x, f = threadIdx.x;
    int s = g_gstart[g], e = g_gstart[g + 1];
    float GS = g_GS[g * DH + f], GB = g_GB[g * DH + f];
    float acc = 0.f;
#pragma unroll 4
    for (int r = s; r < e; ++r) {
        float val = selu_f(fmaf(g_z2[(size_t)r * DH + f], GS, GB));
        g_h[(size_t)r * DH + f] = val;
        acc += val;
    }
    out[(size_t)g * H4 + l * DH + f] = acc * g_invcnt[g];
}

// ---------------- launch ----------------
extern "C" void kernel_launch(void* const* d_in, const int* in_sizes, int n_in,
                              void* d_out, int out_size) {
    const float* x    = (const float*)d_in[0];
    const float* W1   = (const float*)d_in[1];
    const float* bn_g = (const float*)d_in[2];
    const float* bn_b = (const float*)d_in[3];
    const float* W2   = (const float*)d_in[4];
    const float* b2   = (const float*)d_in[5];
    const float* gn_g = (const float*)d_in[6];
    const float* gn_b = (const float*)d_in[7];
    const float* gn_a = (const float*)d_in[8];
    const void*  ei   = d_in[9];
    const void*  batch= d_in[10];
    int N = in_sizes[0] / DH;
    int E = in_sizes[9] / 2;
    float* out = (float*)d_out;

    float *pA, *pz1, *pz2, *ph, *pbn;
    int* pcur;
    cudaGetSymbolAddress((void**)&pA,  g_A);
    cudaGetSymbolAddress((void**)&pz1, g_z1);
    cudaGetSymbolAddress((void**)&pz2, g_z2);
    cudaGetSymbolAddress((void**)&ph,  g_h);
    cudaGetSymbolAddress((void**)&pbn, g_bnstat);
    cudaGetSymbolAddress((void**)&pcur, g_cursor);

    cudaFuncSetAttribute(mgemm<1, 0>, cudaFuncAttributeMaxDynamicSharedMemorySize, SMEM_GEMM);
    cudaFuncSetAttribute(mgemm<2, 1>, cudaFuncAttributeMaxDynamicSharedMemorySize, SMEM_GEMM);

    detect_kernel<<<1, 32>>>(ei);
    zero_i_k<<<(N + 255) / 256, 256>>>(pcur, N);
    hist_kernel<<<(E + 255) / 256, 256>>>(ei, E);
    int nb = (N + 1023) / 1024;
    scan1_kernel<<<nb, 1024>>>(N);
    scan2_kernel<<<1, 32>>>(nb);
    scan3_kernel<<<(N + 255) / 256, 256>>>(N);
    zero_i_k<<<(N + 255) / 256, 256>>>(pcur, N);
    scatter_kernel<<<(E + 255) / 256, 256>>>(ei, E);
    gstart_kernel<<<2, 256>>>(batch, N);
    invcnt_kernel<<<1, 256>>>();

    int gm = (N + 127) / 128;
    for (int l = 0; l < 4; l++) {
        const float* hin = l ? (const float*)ph : x;
        agg_kernel<<<(N + 7) / 8, 256>>>(hin, N);
        zero_f_k<<<4, 256>>>(pbn, 2 * H4);
        // GEMM1: z1[N,512] = A @ W1^T, BN stats in epilogue
        mgemm<1, 0><<<dim3(4, gm), 256, SMEM_GEMM>>>(
            pA, W1 + (size_t)l * H4 * DH, pz1, N, DH, H4, nullptr);
        bnfin_kernel<<<1, 512>>>(bn_g + l * H4, bn_b + l * H4, (float)N);
        // GEMM2: z2[N,128] = selu(BN(z1)) @ W2^T + b2 (BN+SELU fused in loader)
        mgemm<2, 1><<<dim3(1, gm), 256, SMEM_GEMM>>>(
            pz1, W2 + (size_t)l * DH * H4, pz2, N, H4, DH, b2 + l * DH);
        gmean_kernel<<<NG, 128>>>();
        gvar_kernel<<<NG, 128>>>(gn_g + l * DH, gn_b + l * DH, gn_a + l * DH);
        final_kernel<<<NG, 128>>>(out, l);
    }
}

// round 5
// speedup vs baseline: 1.7212x; 1.4196x over previous
#include <cuda_runtime.h>
#include <cuda_bf16.h>
#include <mma.h>
#include <cstdint>
#include <cstddef>

#define NMAX 100000
#define EMAX 600000
#define NG   256
#define DH   128
#define H4   512
#define BN_EPS 1e-5f
#define GN_EPS 1e-5f

using namespace nvcuda;

// ---------------- static device scratch ----------------
static __device__ float g_A [(size_t)NMAX * DH];
static __device__ float g_z1[(size_t)NMAX * H4];
static __device__ float g_z2[(size_t)NMAX * DH];
static __device__ float g_h [(size_t)NMAX * DH];
static __device__ int   g_rowptr[NMAX + 1];
static __device__ int   g_cursor[NMAX];
static __device__ int   g_colidx[EMAX];
static __device__ int   g_bsum[128];
static __device__ int   g_boff[128];
static __device__ int   g_gstart[NG + 1];
static __device__ float g_invcnt[NG];
static __device__ float g_bnstat[2 * H4];
static __device__ float g_scale[H4];
static __device__ float g_shift[H4];
static __device__ float g_GS[NG * DH];
static __device__ float g_GB[NG * DH];
static __device__ int   g_i64;

// ---------------- helpers ----------------
__device__ __forceinline__ float selu_f(float x) {
    const float lam = 1.0507009873554805f;
    const float la  = 1.7580993408473766f;
    return x > 0.f ? lam * x : la * (__expf(x) - 1.f);
}
__device__ __forceinline__ int readIdx(const void* p, long long i) {
    return g_i64 ? (int)((const long long*)p)[i] : ((const int*)p)[i];
}
__device__ __forceinline__ void split2(float a, float b, uint32_t& hi, uint32_t& lo) {
    uint32_t h;
    asm("cvt.rn.bf16x2.f32 %0, %1, %2;" : "=r"(h) : "f"(b), "f"(a));
    float fa = __uint_as_float(h << 16);
    float fb = __uint_as_float(h & 0xffff0000u);
    float ra = a - fa, rb = b - fb;
    uint32_t l;
    asm("cvt.rn.bf16x2.f32 %0, %1, %2;" : "=r"(l) : "f"(rb), "f"(ra));
    hi = h; lo = l;
}

// smem layout: two buffer sets, each {Ah, Al, Bh, Bl} 128x64 bf16 padded tiles
#define LDA 72
#define TILE_B (128 * LDA * 2)          // 18432 bytes per tile
#define BUFSET (4 * TILE_B)             // 73728 bytes per set
#define SMEM_GEMM (2 * BUFSET)          // 147456
#define LDC 132

// phase 1: gmem -> regs
__device__ __forceinline__ void ldg_tile(const float* __restrict__ src, int ld,
                                         int rowBase, int rowLim, int kbase,
                                         int tid, float v[4][8]) {
#pragma unroll
    for (int i = 0; i < 4; i++) {
        int c = tid + i * 256;
        int row = c >> 3, k8 = c & 7;
        int gr = rowBase + row;
        if (gr < rowLim) {
            const float4* p = (const float4*)(src + (size_t)gr * ld + kbase + k8 * 8);
            float4 u0 = p[0], u1 = p[1];
            v[i][0] = u0.x; v[i][1] = u0.y; v[i][2] = u0.z; v[i][3] = u0.w;
            v[i][4] = u1.x; v[i][5] = u1.y; v[i][6] = u1.z; v[i][7] = u1.w;
        } else {
#pragma unroll
            for (int j = 0; j < 8; j++) v[i][j] = 0.f;
        }
    }
}
// phase 2: regs -> (optional BN+SELU) -> split -> smem
template <int PRO>
__device__ __forceinline__ void st_tile(float v[4][8], int kbase,
                                        __nv_bfloat16* dhi, __nv_bfloat16* dlo,
                                        int tid) {
#pragma unroll
    for (int i = 0; i < 4; i++) {
        int c = tid + i * 256;
        int row = c >> 3, k8 = c & 7;
        if (PRO) {
            int col = kbase + k8 * 8;
#pragma unroll
            for (int j = 0; j < 8; j++)
                v[i][j] = selu_f(fmaf(v[i][j], g_scale[col + j], g_shift[col + j]));
        }
        uint32_t h[4], l[4];
#pragma unroll
        for (int j = 0; j < 4; j++) split2(v[i][2 * j], v[i][2 * j + 1], h[j], l[j]);
        *(uint4*)(dhi + row * LDA + k8 * 8) = make_uint4(h[0], h[1], h[2], h[3]);
        *(uint4*)(dlo + row * LDA + k8 * 8) = make_uint4(l[0], l[1], l[2], l[3]);
    }
}

// ---------------- pipelined WMMA split-bf16 GEMM ----------------
// C[M,Ncols] = A[M,K] @ B[Ncols,K]^T.  EPI 1: +BN stats. EPI 2: +bias.
template <int EPI, int PRO>
__global__ void __launch_bounds__(256)
mgemm(const float* __restrict__ A, const float* __restrict__ B, float* __restrict__ C,
      int M, int K, int Ncols, const float* __restrict__ bias) {
    extern __shared__ char sm[];
    int tid = threadIdx.x;
    int w = tid >> 5;
    int m0 = (w >> 2) * 64;
    int n0 = (w & 3) * 32;
    int rowBase = blockIdx.y * 128;
    int colBase = blockIdx.x * 128;

    wmma::fragment<wmma::accumulator, 16, 16, 16, float> acc[4][2];
#pragma unroll
    for (int mi = 0; mi < 4; mi++)
#pragma unroll
        for (int ni = 0; ni < 2; ni++) wmma::fill_fragment(acc[mi][ni], 0.f);

    float va[4][8], vb[4][8];
    int nch = K >> 6;

    // prologue: chunk 0 -> buffer set 0
    ldg_tile(A, K, rowBase, M, 0, tid, va);
    ldg_tile(B, K, colBase, 1 << 30, 0, tid, vb);
    {
        char* b0 = sm;
        st_tile<PRO>(va, 0, (__nv_bfloat16*)b0, (__nv_bfloat16*)(b0 + TILE_B), tid);
        st_tile<0>(vb, 0, (__nv_bfloat16*)(b0 + 2 * TILE_B), (__nv_bfloat16*)(b0 + 3 * TILE_B), tid);
    }
    __syncthreads();

    for (int ch = 0; ch < nch; ch++) {
        int cur = ch & 1;
        if (ch + 1 < nch) {
            ldg_tile(A, K, rowBase, M, (ch + 1) * 64, tid, va);
            ldg_tile(B, K, colBase, 1 << 30, (ch + 1) * 64, tid, vb);
        }
        char* bc = sm + cur * BUFSET;
        __nv_bfloat16* Ah = (__nv_bfloat16*)bc;
        __nv_bfloat16* Al = (__nv_bfloat16*)(bc + TILE_B);
        __nv_bfloat16* Bh = (__nv_bfloat16*)(bc + 2 * TILE_B);
        __nv_bfloat16* Bl = (__nv_bfloat16*)(bc + 3 * TILE_B);
#pragma unroll
        for (int ks = 0; ks < 4; ks++) {
            wmma::fragment<wmma::matrix_b, 16, 16, 16, __nv_bfloat16, wmma::col_major> bh[2], bl[2];
#pragma unroll
            for (int ni = 0; ni < 2; ni++) {
                wmma::load_matrix_sync(bh[ni], Bh + (n0 + 16 * ni) * LDA + ks * 16, LDA);
                wmma::load_matrix_sync(bl[ni], Bl + (n0 + 16 * ni) * LDA + ks * 16, LDA);
            }
#pragma unroll
            for (int mi = 0; mi < 4; mi++) {
                wmma::fragment<wmma::matrix_a, 16, 16, 16, __nv_bfloat16, wmma::row_major> ah, al;
                wmma::load_matrix_sync(ah, Ah + (m0 + 16 * mi) * LDA + ks * 16, LDA);
                wmma::load_matrix_sync(al, Al + (m0 + 16 * mi) * LDA + ks * 16, LDA);
#pragma unroll
                for (int ni = 0; ni < 2; ni++) {
                    wmma::mma_sync(acc[mi][ni], ah, bh[ni], acc[mi][ni]);
                    wmma::mma_sync(acc[mi][ni], ah, bl[ni], acc[mi][ni]);
                    wmma::mma_sync(acc[mi][ni], al, bh[ni], acc[mi][ni]);
                }
            }
        }
        if (ch + 1 < nch) {
            char* bn = sm + ((ch + 1) & 1) * BUFSET;
            st_tile<PRO>(va, (ch + 1) * 64, (__nv_bfloat16*)bn, (__nv_bfloat16*)(bn + TILE_B), tid);
            st_tile<0>(vb, (ch + 1) * 64, (__nv_bfloat16*)(bn + 2 * TILE_B),
                       (__nv_bfloat16*)(bn + 3 * TILE_B), tid);
        }
        __syncthreads();
    }

    // -------- epilogue --------
    float* Csm = (float*)sm;
#pragma unroll
    for (int mi = 0; mi < 4; mi++)
#pragma unroll
        for (int ni = 0; ni < 2; ni++)
            wmma::store_matrix_sync(Csm + (m0 + 16 * mi) * LDC + n0 + 16 * ni,
                                    acc[mi][ni], LDC, wmma::mem_row_major);
    __syncthreads();
    {
        int row = tid >> 1;
        int cb = (tid & 1) * 64;
        int grow = rowBase + row;
        if (grow < M) {
            float* dst = C + (size_t)grow * Ncols + colBase + cb;
            const float* srcr = Csm + row * LDC + cb;
#pragma unroll
            for (int j = 0; j < 64; j += 4) {
                float4 v = *(const float4*)(srcr + j);
                if (EPI == 2) {
                    v.x += __ldg(&bias[colBase + cb + j + 0]);
                    v.y += __ldg(&bias[colBase + cb + j + 1]);
                    v.z += __ldg(&bias[colBase + cb + j + 2]);
                    v.w += __ldg(&bias[colBase + cb + j + 3]);
                }
                *(float4*)(dst + j) = v;
            }
        }
    }
    if (EPI == 1) {
        int c = tid & 127;
        int r0 = (tid >> 7) * 64;
        float s = 0.f, q = 0.f;
#pragma unroll 4
        for (int r = r0; r < r0 + 64; r++) {
            float v = Csm[r * LDC + c];
            s += v; q += v * v;
        }
        atomicAdd(&g_bnstat[colBase + c], s);
        atomicAdd(&g_bnstat[H4 + colBase + c], q);
    }
}

// ---------------- tiny utility kernels ----------------
__global__ void zero_f_k(float* p, int n) {
    int i = blockIdx.x * blockDim.x + threadIdx.x;
    if (i < n) p[i] = 0.f;
}
__global__ void zero_i_k(int* p, int n) {
    int i = blockIdx.x * blockDim.x + threadIdx.x;
    if (i < n) p[i] = 0;
}
__global__ void detect_kernel(const void* ei) {
    if (threadIdx.x == 0) {
        const long long* p = (const long long*)ei;
        int ok = 1;
        for (int i = 0; i < 64; i++) {
            long long v = p[i];
            if (v < 0 || v >= (1LL << 31)) ok = 0;
        }
        g_i64 = ok;
    }
}

// ---------------- CSR build ----------------
__global__ void hist_kernel(const void* ei, int E) {
    int e = blockIdx.x * blockDim.x + threadIdx.x;
    if (e < E) atomicAdd(&g_cursor[readIdx(ei, (long long)E + e)], 1);
}
__global__ void scan1_kernel(int n) {
    __shared__ int s[1024];
    int tid = threadIdx.x;
    int i = blockIdx.x * 1024 + tid;
    int v = (i < n) ? g_cursor[i] : 0;
    s[tid] = v;
    __syncthreads();
    for (int off = 1; off < 1024; off <<= 1) {
        int t = 0;
        if (tid >= off) t = s[tid - off];
        __syncthreads();
        s[tid] += t;
        __syncthreads();
    }
    if (i < n) g_rowptr[i + 1] = s[tid];
    if (tid == 1023) g_bsum[blockIdx.x] = s[1023];
}
__global__ void scan2_kernel(int nb) {
    if (threadIdx.x == 0) {
        int run = 0;
        for (int b = 0; b < nb; b++) { g_boff[b] = run; run += g_bsum[b]; }
    }
}
__global__ void scan3_kernel(int n) {
    int i = blockIdx.x * blockDim.x + threadIdx.x;
    if (i < n) g_rowptr[i + 1] += g_boff[i >> 10];
    if (i == 0) g_rowptr[0] = 0;
}
__global__ void scatter_kernel(const void* ei, int E) {
    int e = blockIdx.x * blockDim.x + threadIdx.x;
    if (e >= E) return;
    int d = readIdx(ei, (long long)E + e);
    int slot = g_rowptr[d] + atomicAdd(&g_cursor[d], 1);
    g_colidx[slot] = readIdx(ei, e);
}

// ---------------- graph ranges ----------------
__global__ void gstart_kernel(const void* batch, int n) {
    int g = blockIdx.x * blockDim.x + threadIdx.x;
    if (g > NG) return;
    int lo = 0, hi = n;
    while (lo < hi) {
        int mid = (lo + hi) >> 1;
        if (readIdx(batch, mid) < g) lo = mid + 1; else hi = mid;
    }
    g_gstart[g] = lo;
}
__global__ void invcnt_kernel() {
    int g = threadIdx.x;
    if (g < NG) {
        int c = g_gstart[g + 1] - g_gstart[g];
        g_invcnt[g] = 1.f / fmaxf((float)c, 1.f);
    }
}

// ---------------- GIN aggregation ----------------
__global__ void agg_kernel(const float* __restrict__ h, int N) {
    int warp = (blockIdx.x * blockDim.x + threadIdx.x) >> 5;
    int lane = threadIdx.x & 31;
    if (warp >= N) return;
    float4 acc = __ldg((const float4*)(h + (size_t)warp * DH) + lane);
    int s = g_rowptr[warp], e = g_rowptr[warp + 1];
    for (int p = s; p < e; ++p) {
        int nb = g_colidx[p];
        float4 v = __ldg((const float4*)(h + (size_t)nb * DH) + lane);
        acc.x += v.x; acc.y += v.y; acc.z += v.z; acc.w += v.w;
    }
    ((float4*)(g_A + (size_t)warp * DH))[lane] = acc;
}

// ---------------- BN finalize ----------------
__global__ void bnfin_kernel(const float* __restrict__ bn_g,
                             const float* __restrict__ bn_b, float fN) {
    int o = blockIdx.x * blockDim.x + threadIdx.x;
    if (o >= H4) return;
    float mu = g_bnstat[o] / fN;
    float var = fmaxf(g_bnstat[H4 + o] / fN - mu * mu, 0.f);
    float rstd = rsqrtf(var + BN_EPS);
    float sc = bn_g[o] * rstd;
    g_scale[o] = sc;
    g_shift[o] = bn_b[o] - mu * sc;
}

// ---------------- GraphNorm: single-pass sum+sumsq -> GS/GB ----------------
__global__ void gnorm_kernel(const float* __restrict__ gn_g,
                             const float* __restrict__ gn_b,
                             const float* __restrict__ gn_a) {
    __shared__ float S[4][DH], Q[4][DH];
    int g = blockIdx.x, t = threadIdx.x;
    int f = t & 127, sl = t >> 7;
    int s = g_gstart[g], e = g_gstart[g + 1];
    float sum = 0.f, sq = 0.f;
    for (int r = s + sl; r < e; r += 4) {
        float v = g_z2[(size_t)r * DH + f];
        sum += v; sq += v * v;
    }
    S[sl][f] = sum; Q[sl][f] = sq;
    __syncthreads();
    if (t < DH) {
        float sm = S[0][f] + S[1][f] + S[2][f] + S[3][f];
        float qm = Q[0][f] + Q[1][f] + Q[2][f] + Q[3][f];
        float ic = g_invcnt[g];
        float mu = sm * ic;
        float am = gn_a[f] * mu;
        float var = fmaxf(qm * ic - 2.f * am * mu + am * am, 0.f);
        float rstd = rsqrtf(var + GN_EPS);
        float GS = gn_g[f] * rstd;
        g_GS[g * DH + f] = GS;
        g_GB[g * DH + f] = gn_b[f] - am * GS;
    }
}
__global__ void final_kernel(float* __restrict__ out, int l) {
    __shared__ float S[4][DH];
    int g = blockIdx.x, t = threadIdx.x;
    int f = t & 127, sl = t >> 7;
    int s = g_gstart[g], e = g_gstart[g + 1];
    float GS = g_GS[g * DH + f], GB = g_GB[g * DH + f];
    float acc = 0.f;
    for (int r = s + sl; r < e; r += 4) {
        float val = selu_f(fmaf(g_z2[(size_t)r * DH + f], GS, GB));
        g_h[(size_t)r * DH + f] = val;
        acc += val;
    }
    S[sl][f] = acc;
    __syncthreads();
    if (t < DH)
        out[(size_t)g * H4 + l * DH + f] =
            (S[0][f] + S[1][f] + S[2][f] + S[3][f]) * g_invcnt[g];
}

// ---------------- launch ----------------
extern "C" void kernel_launch(void* const* d_in, const int* in_sizes, int n_in,
                              void* d_out, int out_size) {
    const float* x    = (const float*)d_in[0];
    const float* W1   = (const float*)d_in[1];
    const float* bn_g = (const float*)d_in[2];
    const float* bn_b = (const float*)d_in[3];
    const float* W2   = (const float*)d_in[4];
    const float* b2   = (const float*)d_in[5];
    const float* gn_g = (const float*)d_in[6];
    const float* gn_b = (const float*)d_in[7];
    const float* gn_a = (const float*)d_in[8];
    const void*  ei   = d_in[9];
    const void*  batch= d_in[10];
    int N = in_sizes[0] / DH;
    int E = in_sizes[9] / 2;
    float* out = (float*)d_out;

    float *pA, *pz1, *pz2, *ph, *pbn;
    int* pcur;
    cudaGetSymbolAddress((void**)&pA,  g_A);
    cudaGetSymbolAddress((void**)&pz1, g_z1);
    cudaGetSymbolAddress((void**)&pz2, g_z2);
    cudaGetSymbolAddress((void**)&ph,  g_h);
    cudaGetSymbolAddress((void**)&pbn, g_bnstat);
    cudaGetSymbolAddress((void**)&pcur, g_cursor);

    cudaFuncSetAttribute(mgemm<1, 0>, cudaFuncAttributeMaxDynamicSharedMemorySize, SMEM_GEMM);
    cudaFuncSetAttribute(mgemm<2, 1>, cudaFuncAttributeMaxDynamicSharedMemorySize, SMEM_GEMM);

    detect_kernel<<<1, 32>>>(ei);
    zero_i_k<<<(N + 255) / 256, 256>>>(pcur, N);
    hist_kernel<<<(E + 255) / 256, 256>>>(ei, E);
    int nb = (N + 1023) / 1024;
    scan1_kernel<<<nb, 1024>>>(N);
    scan2_kernel<<<1, 32>>>(nb);
    scan3_kernel<<<(N + 255) / 256, 256>>>(N);
    zero_i_k<<<(N + 255) / 256, 256>>>(pcur, N);
    scatter_kernel<<<(E + 255) / 256, 256>>>(ei, E);
    gstart_kernel<<<2, 256>>>(batch, N);
    invcnt_kernel<<<1, 256>>>();

    int gm = (N + 127) / 128;
    for (int l = 0; l < 4; l++) {
        const float* hin = l ? (const float*)ph : x;
        agg_kernel<<<(N + 7) / 8, 256>>>(hin, N);
        zero_f_k<<<4, 256>>>(pbn, 2 * H4);
        mgemm<1, 0><<<dim3(4, gm), 256, SMEM_GEMM>>>(
            pA, W1 + (size_t)l * H4 * DH, pz1, N, DH, H4, nullptr);
        bnfin_kernel<<<1, 512>>>(bn_g + l * H4, bn_b + l * H4, (float)N);
        mgemm<2, 1><<<dim3(1, gm), 256, SMEM_GEMM>>>(
            pz1, W2 + (size_t)l * DH * H4, pz2, N, H4, DH, b2 + l * DH);
        gnorm_kernel<<<NG, 512>>>(gn_g + l * DH, gn_b + l * DH, gn_a + l * DH);
        final_kernel<<<NG, 512>>>(out, l);
    }
}

// round 6
// speedup vs baseline: 1.7919x; 1.0411x over previous
#include <cuda_runtime.h>
#include <cuda_bf16.h>
#include <mma.h>
#include <cstdint>
#include <cstddef>

#define NMAX 100000
#define EMAX 600000
#define NG   256
#define DH   128
#define H4   512
#define BN_EPS 1e-5f
#define GN_EPS 1e-5f

using namespace nvcuda;

// ---------------- static device scratch ----------------
static __device__ __nv_bfloat16 g_Ah[(size_t)NMAX * DH];
static __device__ __nv_bfloat16 g_Al[(size_t)NMAX * DH];
static __device__ float g_z1[(size_t)NMAX * H4];
static __device__ float g_z2[(size_t)NMAX * DH];
static __device__ float g_h [(size_t)NMAX * DH];
static __device__ __nv_bfloat16 g_W1h[4 * H4 * DH];
static __device__ __nv_bfloat16 g_W1l[4 * H4 * DH];
static __device__ __nv_bfloat16 g_W2h[4 * DH * H4];
static __device__ __nv_bfloat16 g_W2l[4 * DH * H4];
static __device__ int   g_rowptr[NMAX + 1];
static __device__ int   g_cursor[NMAX];
static __device__ int   g_colidx[EMAX];
static __device__ int   g_bsum[128];
static __device__ int   g_boff[128];
static __device__ int   g_gstart[NG + 1];
static __device__ float g_invcnt[NG];
static __device__ float g_bnstat[2 * H4];
static __device__ float g_scale[H4];
static __device__ float g_shift[H4];
static __device__ float g_GS[NG * DH];
static __device__ float g_GB[NG * DH];
static __device__ int   g_i64;

// ---------------- helpers ----------------
__device__ __forceinline__ float selu_f(float x) {
    const float lam = 1.0507009873554805f;
    const float la  = 1.7580993408473766f;
    return x > 0.f ? lam * x : la * (__expf(x) - 1.f);
}
__device__ __forceinline__ int readIdx(const void* p, long long i) {
    return g_i64 ? (int)((const long long*)p)[i] : ((const int*)p)[i];
}
__device__ __forceinline__ void split2(float a, float b, uint32_t& hi, uint32_t& lo) {
    uint32_t h;
    asm("cvt.rn.bf16x2.f32 %0, %1, %2;" : "=r"(h) : "f"(b), "f"(a));
    float fa = __uint_as_float(h << 16);
    float fb = __uint_as_float(h & 0xffff0000u);
    float ra = a - fa, rb = b - fb;
    uint32_t l;
    asm("cvt.rn.bf16x2.f32 %0, %1, %2;" : "=r"(l) : "f"(rb), "f"(ra));
    hi = h; lo = l;
}
// cp.async 16B with src-size (0 -> zero-fill)
__device__ __forceinline__ void cpa16(uint32_t dst, const void* src, int srcsz) {
    asm volatile("cp.async.cg.shared.global [%0], [%1], 16, %2;"
                 :: "r"(dst), "l"(src), "r"(srcsz));
}
#define CPA_COMMIT() asm volatile("cp.async.commit_group;" ::: "memory")
#define CPA_WAIT0()  asm volatile("cp.async.wait_group 0;" ::: "memory")
#define CPA_WAIT1()  asm volatile("cp.async.wait_group 1;" ::: "memory")

// smem: two buffer sets, each {Ah, Al, Bh, Bl} 128x64 bf16 padded tiles
#define LDA 72
#define LDAB (LDA * 2)                  // 144 bytes per smem tile row
#define TILE_B (128 * LDAB)             // 18432
#define BUFSET (4 * TILE_B)             // 73728
#define SMEM_GEMM (2 * BUFSET)          // 147456
#define LDC 132

// ---------------- GEMM1: all-copy loader (pre-split A and B) ----------------
__device__ __forceinline__ void issue4(const __nv_bfloat16* __restrict__ Ah,
                                       const __nv_bfloat16* __restrict__ Al,
                                       const __nv_bfloat16* __restrict__ Bh,
                                       const __nv_bfloat16* __restrict__ Bl,
                                       int K, int rowBase, int M, int colBase,
                                       int kbase, uint32_t sb, int tid) {
#pragma unroll
    for (int i = 0; i < 4; i++) {
        int c = tid + i * 256;
        int row = c >> 3, k8 = c & 7;
        uint32_t doff = (uint32_t)(row * LDAB + k8 * 16);
        size_t aoff = (size_t)(rowBase + row) * K + kbase + k8 * 8;
        size_t boff = (size_t)(colBase + row) * K + kbase + k8 * 8;
        int av = (rowBase + row) < M ? 16 : 0;
        cpa16(sb + doff,              Ah + aoff, av);
        cpa16(sb + TILE_B + doff,     Al + aoff, av);
        cpa16(sb + 2 * TILE_B + doff, Bh + boff, 16);
        cpa16(sb + 3 * TILE_B + doff, Bl + boff, 16);
    }
    CPA_COMMIT();
}

// shared MMA phase: 8 warps, warp tile 64x32, 3-term split accumulate
__device__ __forceinline__ void mma_chunk(
    char* bc, int m0, int n0,
    wmma::fragment<wmma::accumulator, 16, 16, 16, float> acc[4][2]) {
    __nv_bfloat16* Ah = (__nv_bfloat16*)bc;
    __nv_bfloat16* Al = (__nv_bfloat16*)(bc + TILE_B);
    __nv_bfloat16* Bh = (__nv_bfloat16*)(bc + 2 * TILE_B);
    __nv_bfloat16* Bl = (__nv_bfloat16*)(bc + 3 * TILE_B);
#pragma unroll
    for (int ks = 0; ks < 4; ks++) {
        wmma::fragment<wmma::matrix_b, 16, 16, 16, __nv_bfloat16, wmma::col_major> bh[2], bl[2];
#pragma unroll
        for (int ni = 0; ni < 2; ni++) {
            wmma::load_matrix_sync(bh[ni], Bh + (n0 + 16 * ni) * LDA + ks * 16, LDA);
            wmma::load_matrix_sync(bl[ni], Bl + (n0 + 16 * ni) * LDA + ks * 16, LDA);
        }
#pragma unroll
        for (int mi = 0; mi < 4; mi++) {
            wmma::fragment<wmma::matrix_a, 16, 16, 16, __nv_bfloat16, wmma::row_major> ah, al;
            wmma::load_matrix_sync(ah, Ah + (m0 + 16 * mi) * LDA + ks * 16, LDA);
            wmma::load_matrix_sync(al, Al + (m0 + 16 * mi) * LDA + ks * 16, LDA);
#pragma unroll
            for (int ni = 0; ni < 2; ni++) {
                wmma::mma_sync(acc[mi][ni], ah, bh[ni], acc[mi][ni]);
                wmma::mma_sync(acc[mi][ni], ah, bl[ni], acc[mi][ni]);
                wmma::mma_sync(acc[mi][ni], al, bh[ni], acc[mi][ni]);
            }
        }
    }
}

// GEMM1: z1 = Asplit @ W1split^T, BN stats epilogue.  K=128 (2 chunks).
__global__ void __launch_bounds__(256)
mgemm1(const __nv_bfloat16* __restrict__ Bh, const __nv_bfloat16* __restrict__ Bl,
       float* __restrict__ C, int M, int K, int Ncols) {
    extern __shared__ char sm[];
    uint32_t sb = (uint32_t)__cvta_generic_to_shared(sm);
    int tid = threadIdx.x;
    int w = tid >> 5;
    int m0 = (w >> 2) * 64, n0 = (w & 3) * 32;
    int rowBase = blockIdx.y * 128;
    int colBase = blockIdx.x * 128;

    wmma::fragment<wmma::accumulator, 16, 16, 16, float> acc[4][2];
#pragma unroll
    for (int mi = 0; mi < 4; mi++)
#pragma unroll
        for (int ni = 0; ni < 2; ni++) wmma::fill_fragment(acc[mi][ni], 0.f);

    int nch = K >> 6;
    issue4(g_Ah, g_Al, Bh, Bl, K, rowBase, M, colBase, 0, sb, tid);
    for (int ch = 0; ch < nch; ch++) {
        if (ch + 1 < nch) {
            issue4(g_Ah, g_Al, Bh, Bl, K, rowBase, M, colBase, (ch + 1) * 64,
                   sb + ((ch + 1) & 1) * BUFSET, tid);
            CPA_WAIT1();
        } else {
            CPA_WAIT0();
        }
        __syncthreads();
        mma_chunk(sm + (ch & 1) * BUFSET, m0, n0, acc);
        __syncthreads();
    }

    // epilogue: write C + BN stats
    float* Csm = (float*)sm;
#pragma unroll
    for (int mi = 0; mi < 4; mi++)
#pragma unroll
        for (int ni = 0; ni < 2; ni++)
            wmma::store_matrix_sync(Csm + (m0 + 16 * mi) * LDC + n0 + 16 * ni,
                                    acc[mi][ni], LDC, wmma::mem_row_major);
    __syncthreads();
    {
        int row = tid >> 1;
        int cb = (tid & 1) * 64;
        int grow = rowBase + row;
        if (grow < M) {
            float* dst = C + (size_t)grow * Ncols + colBase + cb;
            const float* srcr = Csm + row * LDC + cb;
#pragma unroll
            for (int j = 0; j < 64; j += 4)
                *(float4*)(dst + j) = *(const float4*)(srcr + j);
        }
    }
    {
        int c = tid & 127;
        int r0 = (tid >> 7) * 64;
        float s = 0.f, q = 0.f;
#pragma unroll 4
        for (int r = r0; r < r0 + 64; r++) {
            float v = Csm[r * LDC + c];
            s += v; q += v * v;
        }
        atomicAdd(&g_bnstat[colBase + c], s);
        atomicAdd(&g_bnstat[H4 + colBase + c], q);
    }
}

// ---------------- GEMM2: A = selu(BN(z1)) fp32->split in regs; B pre-split copy ----
__device__ __forceinline__ void ldgA(const float* __restrict__ src, int ld,
                                     int rowBase, int M, int kbase,
                                     int tid, float v[4][8]) {
#pragma unroll
    for (int i = 0; i < 4; i++) {
        int c = tid + i * 256;
        int row = c >> 3, k8 = c & 7;
        int gr = rowBase + row;
        if (gr < M) {
            const float4* p = (const float4*)(src + (size_t)gr * ld + kbase + k8 * 8);
            float4 u0 = p[0], u1 = p[1];
            v[i][0] = u0.x; v[i][1] = u0.y; v[i][2] = u0.z; v[i][3] = u0.w;
            v[i][4] = u1.x; v[i][5] = u1.y; v[i][6] = u1.z; v[i][7] = u1.w;
        } else {
#pragma unroll
            for (int j = 0; j < 8; j++) v[i][j] = 0.f;
        }
    }
}
__device__ __forceinline__ void stA(float v[4][8], int kbase, char* bc, int tid) {
    __nv_bfloat16* dhi = (__nv_bfloat16*)bc;
    __nv_bfloat16* dlo = (__nv_bfloat16*)(bc + TILE_B);
#pragma unroll
    for (int i = 0; i < 4; i++) {
        int c = tid + i * 256;
        int row = c >> 3, k8 = c & 7;
        int col = kbase + k8 * 8;
#pragma unroll
        for (int j = 0; j < 8; j++)
            v[i][j] = selu_f(fmaf(v[i][j], g_scale[col + j], g_shift[col + j]));
        uint32_t h[4], l[4];
#pragma unroll
        for (int j = 0; j < 4; j++) split2(v[i][2 * j], v[i][2 * j + 1], h[j], l[j]);
        *(uint4*)(dhi + row * LDA + k8 * 8) = make_uint4(h[0], h[1], h[2], h[3]);
        *(uint4*)(dlo + row * LDA + k8 * 8) = make_uint4(l[0], l[1], l[2], l[3]);
    }
}
__device__ __forceinline__ void issueB(const __nv_bfloat16* __restrict__ Bh,
                                       const __nv_bfloat16* __restrict__ Bl,
                                       int K, int colBase, int kbase,
                                       uint32_t sb, int tid) {
#pragma unroll
    for (int i = 0; i < 4; i++) {
        int c = tid + i * 256;
        int row = c >> 3, k8 = c & 7;
        uint32_t doff = (uint32_t)(row * LDAB + k8 * 16);
        size_t boff = (size_t)(colBase + row) * K + kbase + k8 * 8;
        cpa16(sb + 2 * TILE_B + doff, Bh + boff, 16);
        cpa16(sb + 3 * TILE_B + doff, Bl + boff, 16);
    }
    CPA_COMMIT();
}

__global__ void __launch_bounds__(256)
mgemm2(const float* __restrict__ A,
       const __nv_bfloat16* __restrict__ Bh, const __nv_bfloat16* __restrict__ Bl,
       float* __restrict__ C, int M, int K, int Ncols, const float* __restrict__ bias) {
    extern __shared__ char sm[];
    uint32_t sb = (uint32_t)__cvta_generic_to_shared(sm);
    int tid = threadIdx.x;
    int w = tid >> 5;
    int m0 = (w >> 2) * 64, n0 = (w & 3) * 32;
    int rowBase = blockIdx.y * 128;
    int colBase = blockIdx.x * 128;

    wmma::fragment<wmma::accumulator, 16, 16, 16, float> acc[4][2];
#pragma unroll
    for (int mi = 0; mi < 4; mi++)
#pragma unroll
        for (int ni = 0; ni < 2; ni++) wmma::fill_fragment(acc[mi][ni], 0.f);

    float va[4][8];
    int nch = K >> 6;

    ldgA(A, K, rowBase, M, 0, tid, va);
    issueB(Bh, Bl, K, colBase, 0, sb, tid);
    stA(va, 0, sm, tid);

    for (int ch = 0; ch < nch; ch++) {
        if (ch + 1 < nch) {
            ldgA(A, K, rowBase, M, (ch + 1) * 64, tid, va);
            issueB(Bh, Bl, K, colBase, (ch + 1) * 64, sb + ((ch + 1) & 1) * BUFSET, tid);
            CPA_WAIT1();
        } else {
            CPA_WAIT0();
        }
        __syncthreads();
        mma_chunk(sm + (ch & 1) * BUFSET, m0, n0, acc);
        if (ch + 1 < nch) stA(va, (ch + 1) * 64, sm + ((ch + 1) & 1) * BUFSET, tid);
        __syncthreads();
    }

    // epilogue: write C + bias
    float* Csm = (float*)sm;
#pragma unroll
    for (int mi = 0; mi < 4; mi++)
#pragma unroll
        for (int ni = 0; ni < 2; ni++)
            wmma::store_matrix_sync(Csm + (m0 + 16 * mi) * LDC + n0 + 16 * ni,
                                    acc[mi][ni], LDC, wmma::mem_row_major);
    __syncthreads();
    {
        int row = tid >> 1;
        int cb = (tid & 1) * 64;
        int grow = rowBase + row;
        if (grow < M) {
            float* dst = C + (size_t)grow * Ncols + colBase + cb;
            const float* srcr = Csm + row * LDC + cb;
#pragma unroll
            for (int j = 0; j < 64; j += 4) {
                float4 v = *(const float4*)(srcr + j);
                v.x += __ldg(&bias[colBase + cb + j + 0]);
                v.y += __ldg(&bias[colBase + cb + j + 1]);
                v.z += __ldg(&bias[colBase + cb + j + 2]);
                v.w += __ldg(&bias[colBase + cb + j + 3]);
                *(float4*)(dst + j) = v;
            }
        }
    }
}

// ---------------- weight pre-split ----------------
__global__ void presplit_k(const float* __restrict__ W,
                           __nv_bfloat16* __restrict__ Wh,
                           __nv_bfloat16* __restrict__ Wl, int n2) {
    int i = blockIdx.x * blockDim.x + threadIdx.x;
    if (i >= n2) return;
    float2 v = *(const float2*)(W + 2 * i);
    uint32_t h, l;
    split2(v.x, v.y, h, l);
    ((uint32_t*)Wh)[i] = h;
    ((uint32_t*)Wl)[i] = l;
}

// ---------------- tiny utility kernels ----------------
__global__ void zero_f_k(float* p, int n) {
    int i = blockIdx.x * blockDim.x + threadIdx.x;
    if (i < n) p[i] = 0.f;
}
__global__ void zero_i_k(int* p, int n) {
    int i = blockIdx.x * blockDim.x + threadIdx.x;
    if (i < n) p[i] = 0;
}
__global__ void detect_kernel(const void* ei) {
    if (threadIdx.x == 0) {
        const long long* p = (const long long*)ei;
        int ok = 1;
        for (int i = 0; i < 64; i++) {
            long long v = p[i];
            if (v < 0 || v >= (1LL << 31)) ok = 0;
        }
        g_i64 = ok;
    }
}

// ---------------- CSR build ----------------
__global__ void hist_kernel(const void* ei, int E) {
    int e = blockIdx.x * blockDim.x + threadIdx.x;
    if (e < E) atomicAdd(&g_cursor[readIdx(ei, (long long)E + e)], 1);
}
__global__ void scan1_kernel(int n) {
    __shared__ int s[1024];
    int tid = threadIdx.x;
    int i = blockIdx.x * 1024 + tid;
    int v = (i < n) ? g_cursor[i] : 0;
    s[tid] = v;
    __syncthreads();
    for (int off = 1; off < 1024; off <<= 1) {
        int t = 0;
        if (tid >= off) t = s[tid - off];
        __syncthreads();
        s[tid] += t;
        __syncthreads();
    }
    if (i < n) g_rowptr[i + 1] = s[tid];
    if (tid == 1023) g_bsum[blockIdx.x] = s[1023];
}
__global__ void scan2_kernel(int nb) {
    if (threadIdx.x == 0) {
        int run = 0;
        for (int b = 0; b < nb; b++) { g_boff[b] = run; run += g_bsum[b]; }
    }
}
__global__ void scan3_kernel(int n) {
    int i = blockIdx.x * blockDim.x + threadIdx.x;
    if (i < n) g_rowptr[i + 1] += g_boff[i >> 10];
    if (i == 0) g_rowptr[0] = 0;
}
__global__ void scatter_kernel(const void* ei, int E) {
    int e = blockIdx.x * blockDim.x + threadIdx.x;
    if (e >= E) return;
    int d = readIdx(ei, (long long)E + e);
    int slot = g_rowptr[d] + atomicAdd(&g_cursor[d], 1);
    g_colidx[slot] = readIdx(ei, e);
}

// ---------------- graph ranges ----------------
__global__ void gstart_kernel(const void* batch, int n) {
    int g = blockIdx.x * blockDim.x + threadIdx.x;
    if (g > NG) return;
    int lo = 0, hi = n;
    while (lo < hi) {
        int mid = (lo + hi) >> 1;
        if (readIdx(batch, mid) < g) lo = mid + 1; else hi = mid;
    }
    g_gstart[g] = lo;
}
__global__ void invcnt_kernel() {
    int g = threadIdx.x;
    if (g < NG) {
        int c = g_gstart[g + 1] - g_gstart[g];
        g_invcnt[g] = 1.f / fmaxf((float)c, 1.f);
    }
}

// ---------------- GIN aggregation -> split bf16 A ----------------
__global__ void agg_kernel(const float* __restrict__ h, int N) {
    int warp = (blockIdx.x * blockDim.x + threadIdx.x) >> 5;
    int lane = threadIdx.x & 31;
    if (warp >= N) return;
    float4 acc = __ldg((const float4*)(h + (size_t)warp * DH) + lane);
    int s = g_rowptr[warp], e = g_rowptr[warp + 1];
    for (int p = s; p < e; ++p) {
        int nb = g_colidx[p];
        float4 v = __ldg((const float4*)(h + (size_t)nb * DH) + lane);
        acc.x += v.x; acc.y += v.y; acc.z += v.z; acc.w += v.w;
    }
    uint32_t h0, l0, h1, l1;
    split2(acc.x, acc.y, h0, l0);
    split2(acc.z, acc.w, h1, l1);
    ((uint2*)(g_Ah + (size_t)warp * DH))[lane] = make_uint2(h0, h1);
    ((uint2*)(g_Al + (size_t)warp * DH))[lane] = make_uint2(l0, l1);
}

// ---------------- BN finalize ----------------
__global__ void bnfin_kernel(const float* __restrict__ bn_g,
                             const float* __restrict__ bn_b, float fN) {
    int o = blockIdx.x * blockDim.x + threadIdx.x;
    if (o >= H4) return;
    float mu = g_bnstat[o] / fN;
    float var = fmaxf(g_bnstat[H4 + o] / fN - mu * mu, 0.f);
    float rstd = rsqrtf(var + BN_EPS);
    float sc = bn_g[o] * rstd;
    g_scale[o] = sc;
    g_shift[o] = bn_b[o] - mu * sc;
}

// ---------------- GraphNorm ----------------
__global__ void gnorm_kernel(const float* __restrict__ gn_g,
                             const float* __restrict__ gn_b,
                             const float* __restrict__ gn_a) {
    __shared__ float S[4][DH], Q[4][DH];
    int g = blockIdx.x, t = threadIdx.x;
    int f = t & 127, sl = t >> 7;
    int s = g_gstart[g], e = g_gstart[g + 1];
    float sum = 0.f, sq = 0.f;
    for (int r = s + sl; r < e; r += 4) {
        float v = g_z2[(size_t)r * DH + f];
        sum += v; sq += v * v;
    }
    S[sl][f] = sum; Q[sl][f] = sq;
    __syncthreads();
    if (t < DH) {
        float sm = S[0][f] + S[1][f] + S[2][f] + S[3][f];
        float qm = Q[0][f] + Q[1][f] + Q[2][f] + Q[3][f];
        float ic = g_invcnt[g];
        float mu = sm * ic;
        float am = gn_a[f] * mu;
        float var = fmaxf(qm * ic - 2.f * am * mu + am * am, 0.f);
        float rstd = rsqrtf(var + GN_EPS);
        float GS = gn_g[f] * rstd;
        g_GS[g * DH + f] = GS;
        g_GB[g * DH + f] = gn_b[f] - am * GS;
    }
}
__global__ void final_kernel(float* __restrict__ out, int l) {
    __shared__ float S[4][DH];
    int g = blockIdx.x, t = threadIdx.x;
    int f = t & 127, sl = t >> 7;
    int s = g_gstart[g], e = g_gstart[g + 1];
    float GS = g_GS[g * DH + f], GB = g_GB[g * DH + f];
    float acc = 0.f;
    for (int r = s + sl; r < e; r += 4) {
        float val = selu_f(fmaf(g_z2[(size_t)r * DH + f], GS, GB));
        g_h[(size_t)r * DH + f] = val;
        acc += val;
    }
    S[sl][f] = acc;
    __syncthreads();
    if (t < DH)
        out[(size_t)g * H4 + l * DH + f] =
            (S[0][f] + S[1][f] + S[2][f] + S[3][f]) * g_invcnt[g];
}

// ---------------- launch ----------------
extern "C" void kernel_launch(void* const* d_in, const int* in_sizes, int n_in,
                              void* d_out, int out_size) {
    const float* x    = (const float*)d_in[0];
    const float* W1   = (const float*)d_in[1];
    const float* bn_g = (const float*)d_in[2];
    const float* bn_b = (const float*)d_in[3];
    const float* W2   = (const float*)d_in[4];
    const float* b2   = (const float*)d_in[5];
    const float* gn_g = (const float*)d_in[6];
    const float* gn_b = (const float*)d_in[7];
    const float* gn_a = (const float*)d_in[8];
    const void*  ei   = d_in[9];
    const void*  batch= d_in[10];
    int N = in_sizes[0] / DH;
    int E = in_sizes[9] / 2;
    float* out = (float*)d_out;

    float *pz1, *pz2, *ph, *pbn;
    int* pcur;
    __nv_bfloat16 *pW1h, *pW1l, *pW2h, *pW2l;
    cudaGetSymbolAddress((void**)&pz1, g_z1);
    cudaGetSymbolAddress((void**)&pz2, g_z2);
    cudaGetSymbolAddress((void**)&ph,  g_h);
    cudaGetSymbolAddress((void**)&pbn, g_bnstat);
    cudaGetSymbolAddress((void**)&pcur, g_cursor);
    cudaGetSymbolAddress((void**)&pW1h, g_W1h);
    cudaGetSymbolAddress((void**)&pW1l, g_W1l);
    cudaGetSymbolAddress((void**)&pW2h, g_W2h);
    cudaGetSymbolAddress((void**)&pW2l, g_W2l);

    cudaFuncSetAttribute(mgemm1, cudaFuncAttributeMaxDynamicSharedMemorySize, SMEM_GEMM);
    cudaFuncSetAttribute(mgemm2, cudaFuncAttributeMaxDynamicSharedMemorySize, SMEM_GEMM);

    detect_kernel<<<1, 32>>>(ei);
    presplit_k<<<512, 256>>>(W1, pW1h, pW1l, 4 * H4 * DH / 2);
    presplit_k<<<512, 256>>>(W2, pW2h, pW2l, 4 * DH * H4 / 2);
    zero_i_k<<<(N + 255) / 256, 256>>>(pcur, N);
    hist_kernel<<<(E + 255) / 256, 256>>>(ei, E);
    int nb = (N + 1023) / 1024;
    scan1_kernel<<<nb, 1024>>>(N);
    scan2_kernel<<<1, 32>>>(nb);
    scan3_kernel<<<(N + 255) / 256, 256>>>(N);
    zero_i_k<<<(N + 255) / 256, 256>>>(pcur, N);
    scatter_kernel<<<(E + 255) / 256, 256>>>(ei, E);
    gstart_kernel<<<2, 256>>>(batch, N);
    invcnt_kernel<<<1, 256>>>();

    int gm = (N + 127) / 128;
    for (int l = 0; l < 4; l++) {
        const float* hin = l ? (const float*)ph : x;
        agg_kernel<<<(N + 7) / 8, 256>>>(hin, N);
        zero_f_k<<<4, 256>>>(pbn, 2 * H4);
        mgemm1<<<dim3(4, gm), 256, SMEM_GEMM>>>(
            pW1h + (size_t)l * H4 * DH, pW1l + (size_t)l * H4 * DH, pz1, N, DH, H4);
        bnfin_kernel<<<1, 512>>>(bn_g + l * H4, bn_b + l * H4, (float)N);
        mgemm2<<<dim3(1, gm), 256, SMEM_GEMM>>>(
            pz1, pW2h + (size_t)l * DH * H4, pW2l + (size_t)l * DH * H4,
            pz2, N, H4, DH, b2 + l * DH);
        gnorm_kernel<<<NG, 512>>>(gn_g + l * DH, gn_b + l * DH, gn_a + l * DH);
        final_kernel<<<NG, 512>>>(out, l);
    }
}